// round 14
// baseline (speedup 1.0000x reference)
#include <cuda_runtime.h>

// PCEN, single fused kernel: x read ONCE into registers.
//
//   M[t] = a*M[t-1] + s*x[t],  a = 0.975, s = 0.025,  M[0] = x[0]
//   out  = sqrt(x * (M+eps)^(-alpha) + delta) - sqrt(delta)
//
// x: (B=64, T=4000, F=128) fp32. CHUNK=20, NCHUNK=200. Block = 4 consecutive
// chunks of one batch (warp = chunk); 3200 blocks.
//
// Per block:
//  A: each warp loads its 20 rows into registers and computes the zero-state
//     chunk partial (chunk 0 carries the true seed M[0]=x[0]).
//     Partials -> smem + global; publish flag (fence -> syncthreads -> flag).
//  B: wait for the <=5 same-batch predecessor blocks' flags (FLAT wait —
//     partials are purely local, so there is no cross-block value chain).
//     Stage their partials (chunks [c0-KT, c0)) into smem.
//  C: per-warp checkpoint via truncated Horner over KT=20 partials
//     (a^(20*20) ~= 4e-5 -> output error ~2e-5, 50x under the 1e-3 gate;
//     exact combine for chunks <= KT).
//  D: sweep register-cached x, write output with evict-first stores.
// Deadlock-free: waits target lower block IDs only; CWD dispatches IDs in
// order, and publishing precedes waiting in every block.

#define B_LEN   64
#define T_LEN   4000
#define F4      32              // 128 floats = 32 float4 lanes
#define CHUNK   20
#define NCHUNK  200             // T_LEN / CHUNK
#define BLKB    (NCHUNK / 4)    // 50 blocks per batch
#define NBLK    (B_LEN * BLKB)  // 3200
#define KT      20              // truncation window (chunks)
#define NWIN    (KT + 4)        // smem slots: chunks [c0-KT, c0+4)

#define C_S       0.025f
#define C_A       0.975f
#define C_EPS     1e-6f
#define C_NALPHA (-0.98f)
#define C_DELTA   2.0f
#define C_SQRTD   1.41421356237309515f

__device__ float4 g_local[B_LEN * NCHUNK * F4];   // chunk partials, 6.5 MB
__device__ int    g_flag[NBLK];

__device__ __forceinline__ float f_lg2(float v) {
    float r; asm("lg2.approx.f32 %0, %1;" : "=f"(r) : "f"(v)); return r;
}
__device__ __forceinline__ float f_ex2(float v) {
    float r; asm("ex2.approx.f32 %0, %1;" : "=f"(r) : "f"(v)); return r;
}
__device__ __forceinline__ float f_sqrt(float v) {
    float r; asm("sqrt.approx.f32 %0, %1;" : "=f"(r) : "f"(v)); return r;
}
__device__ __forceinline__ float pcen1(float xv, float mv) {
    return f_sqrt(fmaf(xv, f_ex2(C_NALPHA * f_lg2(mv + C_EPS)), C_DELTA)) - C_SQRTD;
}
__device__ __forceinline__ float4 ema4(float4 m, float4 xv) {
    m.x = fmaf(C_A, m.x, C_S * xv.x);
    m.y = fmaf(C_A, m.y, C_S * xv.y);
    m.z = fmaf(C_A, m.z, C_S * xv.z);
    m.w = fmaf(C_A, m.w, C_S * xv.w);
    return m;
}
__device__ __forceinline__ float4 comb4(float aL, float4 I, float4 P) {
    float4 r;
    r.x = fmaf(aL, I.x, P.x);
    r.y = fmaf(aL, I.y, P.y);
    r.z = fmaf(aL, I.z, P.z);
    r.w = fmaf(aL, I.w, P.w);
    return r;
}
__device__ __forceinline__ float a_pow_chunk() {   // a^CHUNK, constant-folded
    double ad = 1.0;
    #pragma unroll
    for (int i = 0; i < CHUNK; ++i) ad *= 0.975;
    return (float)ad;
}

__global__ void pcen_init_flags() {
    int i = blockIdx.x * blockDim.x + threadIdx.x;
    if (i < NBLK) g_flag[i] = 0;
}

__global__ void __launch_bounds__(128)
pcen_fused(const float4* __restrict__ x4, float4* __restrict__ out4) {
    __shared__ float4 sp[NWIN * F4];   // chunk partials [wlo, c0+4), 12 KB

    const int bid = blockIdx.x;
    const int b   = bid / BLKB;
    const int cb  = bid - b * BLKB;
    const int c0  = cb * 4;
    const int w   = threadIdx.x >> 5;
    const int l   = threadIdx.x & 31;
    const int c   = c0 + w;                        // this warp's chunk

    const int wlo   = (c0 > KT) ? (c0 - KT) : 0;   // window start chunk
    const int npred = (c0 - wlo) >> 2;             // predecessor blocks (<=5)

    // ---- Phase A: register-load x, zero-state partial, publish ----
    const size_t base = (size_t)(b * T_LEN + c * CHUNK) * F4 + l;
    const float4* px = x4 + base;

    float4 xr[CHUNK];
    #pragma unroll
    for (int i = 0; i < CHUNK; ++i) xr[i] = px[(size_t)i * F4];

    // c==0: pre-state x[0] makes the uniform update exact (a*x0+s*x0 == x0).
    float4 m = (c == 0) ? xr[0] : make_float4(0.f, 0.f, 0.f, 0.f);
    #pragma unroll
    for (int i = 0; i < CHUNK; ++i) m = ema4(m, xr[i]);

    sp[(c - wlo) * F4 + l] = m;                        // own slots for warps 1-3
    g_local[(size_t)(b * NCHUNK + c) * F4 + l] = m;    // for successor blocks
    __threadfence();
    __syncthreads();
    if (threadIdx.x == 0 && cb < BLKB - 1) {
        *((volatile int*)&g_flag[bid]) = 1;
    }

    // ---- Phase B: flat wait on predecessors, stage their partials ----
    if (npred > 0) {
        if (threadIdx.x < npred) {
            volatile int* f = &g_flag[bid - npred + threadIdx.x];
            while (*f == 0) { }
        }
        __syncthreads();
        __threadfence();
        const float4* gw = &g_local[(size_t)(b * NCHUNK + wlo) * F4];
        for (int i = threadIdx.x; i < npred * 4 * F4; i += 128) {
            sp[i] = gw[i];
        }
        __syncthreads();
    }

    const float aL = a_pow_chunk();

    // ---- Phase C: checkpoint S(c-1) via Horner over the window ----
    if (c == 0) {
        m = xr[0];                                 // exact pre-state
    } else if (c > KT) {
        // fixed KT terms: chunks c-KT .. c-1 -> smem slots w .. w+KT-1
        m = sp[w * F4 + l];
        #pragma unroll 5
        for (int j = w + 1; j < w + KT; ++j) {
            m = comb4(aL, m, sp[j * F4 + l]);
        }
    } else {
        // near the start: exact combine from chunk 0 (wlo == 0)
        m = sp[l];
        for (int j = 1; j <= c - 1; ++j) {
            m = comb4(aL, m, sp[j * F4 + l]);
        }
    }

    // ---- Phase D: sweep register-cached x, write output ----
    float4* po = out4 + base;
    #pragma unroll
    for (int i = 0; i < CHUNK; ++i) {
        m = ema4(m, xr[i]);
        float4 o;
        o.x = pcen1(xr[i].x, m.x);
        o.y = pcen1(xr[i].y, m.y);
        o.z = pcen1(xr[i].z, m.z);
        o.w = pcen1(xr[i].w, m.w);
        __stcs(&po[(size_t)i * F4], o);
    }
}

extern "C" void kernel_launch(void* const* d_in, const int* in_sizes, int n_in,
                              void* d_out, int out_size) {
    const float4* x4 = (const float4*)d_in[0];
    float4* out4 = (float4*)d_out;
    (void)in_sizes; (void)n_in; (void)out_size;

    pcen_init_flags<<<(NBLK + 255) / 256, 256>>>();
    pcen_fused<<<NBLK, 128>>>(x4, out4);
}